// round 3
// baseline (speedup 1.0000x reference)
#include <cuda_runtime.h>
#include <cuda_bf16.h>
#include <math.h>
#include <stdint.h>

#define BB    64
#define INS   10000
#define EXPS  53
#define HID   1500
#define NC    2048
#define KX    1553
#define KXP   1664          // KX zero-padded to multiple of 128
#define S1    23
#define SPAN1 448           // 23*448 = 10304 >= 10000, last split = 144
#define S2    13
#define SPAN2 128           // 13*128 = 1664 exactly

// ---------------- device scratch (no allocs allowed) ----------------
__device__ __align__(16) __nv_bfloat16 g_A1h[BB * INS], g_A1l[BB * INS];
__device__ __align__(16) __nv_bfloat16 g_B1h[HID * INS], g_B1l[HID * INS];
__device__ float g_part1[S1][BB][HID];
__device__ __align__(16) __nv_bfloat16 g_xh[BB * KXP], g_xl[BB * KXP];
__device__ __align__(16) __nv_bfloat16 g_B2h[NC * KXP], g_B2l[NC * KXP];
__device__ float g_part2[S2][BB][NC];
__device__ float g_flat[BB * NC];

__device__ __forceinline__ uint32_t smem_u32(const void* p) {
    uint32_t a;
    asm("{ .reg .u64 t; cvta.to.shared.u64 t, %1; cvt.u32.u64 %0, t; }" : "=r"(a) : "l"(p));
    return a;
}
#define LDX4(r, addr)                                                        \
    asm volatile("ldmatrix.sync.aligned.m8n8.x4.shared.b16 {%0,%1,%2,%3}, [%4];" \
        : "=r"((r)[0]), "=r"((r)[1]), "=r"((r)[2]), "=r"((r)[3]) : "r"(addr))
#define MMA16816(d, a, b)                                                    \
    asm volatile("mma.sync.aligned.m16n8k16.row.col.f32.bf16.bf16.f32 "      \
        "{%0,%1,%2,%3}, {%4,%5,%6,%7}, {%8,%9}, {%0,%1,%2,%3};"              \
        : "+f"((d)[0]), "+f"((d)[1]), "+f"((d)[2]), "+f"((d)[3])             \
        : "r"((a)[0]), "r"((a)[1]), "r"((a)[2]), "r"((a)[3]),                \
          "r"((b)[0]), "r"((b)[1]))

// ---------------------------------------------------------------------------
// HMMA split-K GEMM (bf16 hi/lo split = emulated fp32, 3 products).
// Block: 256 thr, tile M=64 x N=128 x Kchunk=64. Warp = 32(M) x 32(N).
// part[split][m][n] = sum_{k in split} A[m,k] * B[n,k]
// smem: A(h,l) 64x72 bf16, B(h,l) 128x72 bf16 (pad stride 72 elem = 144B).
// ---------------------------------------------------------------------------
__global__ __launch_bounds__(256) void gemm_hmma(
    const __nv_bfloat16* __restrict__ Ah, const __nv_bfloat16* __restrict__ Al, int lda,
    const __nv_bfloat16* __restrict__ Bh, const __nv_bfloat16* __restrict__ Bl, int ldb,
    float* __restrict__ part, int N, int K, int span)
{
    extern __shared__ __align__(16) char sm[];
    const int tid = threadIdx.x, lane = tid & 31, w = tid >> 5;
    const int n0 = blockIdx.x * 128;
    const int k0 = blockIdx.y * span;
    const int kend = min(k0 + span, K);
    const int nch = (kend - k0 + 63) >> 6;

    const int offAh = 0, offAl = 9216, offBh = 18432, offBl = 36864; // bytes
    const uint32_t sbase = smem_u32(sm);

    const int wm = (w & 1) * 32;    // warp M base within tile
    const int wn = (w >> 1) * 32;   // warp N base within tile

    float acc[2][4][4];
    #pragma unroll
    for (int i = 0; i < 2; i++)
        #pragma unroll
        for (int j = 0; j < 4; j++)
            #pragma unroll
            for (int e = 0; e < 4; e++) acc[i][j][e] = 0.f;

    // per-lane ldmatrix row/col selectors (element units)
    const int aRow = lane & 15, aCol = (lane >> 4) * 8;
    const int bRow = (lane & 7) + (lane >> 4) * 8, bCol = ((lane >> 3) & 1) * 8;

    for (int c = 0; c < nch; c++) {
        const int kt = k0 + c * 64;
        __syncthreads();
        // ---- stage chunk into smem: 3072 16B granules, 12 per thread
        for (int i = tid; i < 3072; i += 256) {
            uint4 v = make_uint4(0, 0, 0, 0);
            const __nv_bfloat16* src = nullptr;
            int dst, r, g;
            if (i < 1024) {
                int idx = i & 511; r = idx >> 3; g = idx & 7;
                src = (i < 512 ? Ah : Al) + (size_t)r * lda;
                dst = (i < 512 ? offAh : offAl) + (r * 72 + g * 8) * 2;
            } else {
                int j = i - 1024, idx = j & 1023; r = idx >> 3; g = idx & 7;
                int n = n0 + r;
                if (n < N) src = (j < 1024 ? Bh : Bl) + (size_t)n * ldb;
                dst = (j < 1024 ? offBh : offBl) + (r * 72 + g * 8) * 2;
            }
            int gk = kt + g * 8;
            if (src) {
                if (gk + 8 <= kend) {
                    v = *(const uint4*)(src + gk);
                } else if (gk < kend) {
                    __align__(16) __nv_bfloat16 tmp[8];
                    #pragma unroll
                    for (int e = 0; e < 8; e++)
                        tmp[e] = (gk + e < kend) ? src[gk + e] : __float2bfloat16(0.f);
                    v = *(const uint4*)tmp;
                }
            }
            *(uint4*)(sm + dst) = v;
        }
        __syncthreads();

        // ---- 4 k16 steps: ldmatrix fragments + 24 MMAs each
        #pragma unroll
        for (int ks = 0; ks < 4; ks++) {
            const int kk = ks * 16;
            uint32_t ah[2][4], al[2][4], bh[2][4], bl[2][4];
            #pragma unroll
            for (int mi = 0; mi < 2; mi++) {
                uint32_t ad = sbase + offAh + ((wm + mi * 16 + aRow) * 72 + kk + aCol) * 2;
                LDX4(ah[mi], ad);
                LDX4(al[mi], ad + (offAl - offAh));
            }
            #pragma unroll
            for (int p = 0; p < 2; p++) {
                uint32_t bd = sbase + offBh + ((wn + p * 16 + bRow) * 72 + kk + bCol) * 2;
                LDX4(bh[p], bd);
                LDX4(bl[p], bd + (offBl - offBh));
            }
            #pragma unroll
            for (int mi = 0; mi < 2; mi++)
                #pragma unroll
                for (int ni = 0; ni < 4; ni++) {
                    uint32_t* bhp = &bh[ni >> 1][(ni & 1) * 2];
                    uint32_t* blp = &bl[ni >> 1][(ni & 1) * 2];
                    MMA16816(acc[mi][ni], ah[mi], bhp);
                    MMA16816(acc[mi][ni], ah[mi], blp);
                    MMA16816(acc[mi][ni], al[mi], bhp);
                }
        }
    }

    // ---- epilogue: write split-K partials
    float* pb = part + (size_t)blockIdx.y * 64 * N;
    #pragma unroll
    for (int mi = 0; mi < 2; mi++)
        #pragma unroll
        for (int ni = 0; ni < 4; ni++) {
            int r0 = wm + mi * 16 + (lane >> 2);
            int cc = n0 + wn + ni * 8 + (lane & 3) * 2;
            if (cc < N) {
                pb[r0 * N + cc] = acc[mi][ni][0];
                pb[(r0 + 8) * N + cc] = acc[mi][ni][2];
            }
            if (cc + 1 < N) {
                pb[r0 * N + cc + 1] = acc[mi][ni][1];
                pb[(r0 + 8) * N + cc + 1] = acc[mi][ni][3];
            }
        }
}

// ---------------- conversion kernels ----------------
__global__ void convA(const float* __restrict__ A)
{
    int idx = blockIdx.x * 256 + threadIdx.x;
    if (idx >= BB * INS) return;
    float v = A[idx];
    __nv_bfloat16 h = __float2bfloat16(v);
    g_A1h[idx] = h;
    g_A1l[idx] = __float2bfloat16(v - __bfloat162float(h));
}

// W [K][N] fp32 -> Bh/Bl [N][Kpad] bf16 (transposed, K-contiguous, zero-padded)
__global__ void convBT(const float* __restrict__ W, int K, int Nn,
                       __nv_bfloat16* __restrict__ Bh, __nv_bfloat16* __restrict__ Bl, int Kpad)
{
    __shared__ float t[32][33];
    int k0 = blockIdx.x * 32, n0 = blockIdx.y * 32;
    int tx = threadIdx.x, ty = threadIdx.y;
    #pragma unroll
    for (int j = 0; j < 4; j++) {
        int k = k0 + ty + j * 8, n = n0 + tx;
        t[ty + j * 8][tx] = (k < K && n < Nn) ? W[(size_t)k * Nn + n] : 0.f;
    }
    __syncthreads();
    #pragma unroll
    for (int j = 0; j < 4; j++) {
        int n = n0 + ty + j * 8, k = k0 + tx;
        if (n < Nn && k < Kpad) {
            float v = t[tx][ty + j * 8];
            __nv_bfloat16 h = __float2bfloat16(v);
            Bh[(size_t)n * Kpad + k] = h;
            Bl[(size_t)n * Kpad + k] = __float2bfloat16(v - __bfloat162float(h));
        }
    }
}

// ---------------- fused epilogues ----------------
__global__ void fuse1(const float* __restrict__ b1, const float* __restrict__ expx)
{
    int idx = blockIdx.x * 256 + threadIdx.x;
    if (idx >= BB * KXP) return;
    int b = idx / KXP, n = idx - b * KXP;
    float v;
    if (n < HID) {
        float s = b1[n];
        #pragma unroll
        for (int p = 0; p < S1; p++) s += g_part1[p][b][n];
        v = 0.5f * s * (1.f + erff(s * 0.70710678118654752f));
    } else if (n < KX) {
        v = expx[b * EXPS + (n - HID)];
    } else {
        v = 0.f;
    }
    __nv_bfloat16 h = __float2bfloat16(v);
    g_xh[idx] = h;
    g_xl[idx] = __float2bfloat16(v - __bfloat162float(h));
}

__global__ void fuse2(const float* __restrict__ b2)
{
    int idx = blockIdx.x * 256 + threadIdx.x;
    if (idx >= BB * NC) return;
    int b = idx >> 11, n = idx & (NC - 1);
    float s = b2[n];
    #pragma unroll
    for (int p = 0; p < S2; p++) s += g_part2[p][b][n];
    g_flat[idx] = 1.f / (1.f + expf(-s));
}

// out[b,j] = flat[b,j] * max_i M[i,j]   (exact: flat>0, M>=0)
__global__ void colmax_mul(const float* __restrict__ hpo, float* __restrict__ out)
{
    int j = blockIdx.x * 256 + threadIdx.x;
    float m0 = hpo[j], m1 = hpo[NC + j], m2 = hpo[2 * NC + j], m3 = hpo[3 * NC + j];
    #pragma unroll 4
    for (int i = 4; i < NC; i += 4) {
        m0 = fmaxf(m0, hpo[(size_t)i * NC + j]);
        m1 = fmaxf(m1, hpo[(size_t)(i + 1) * NC + j]);
        m2 = fmaxf(m2, hpo[(size_t)(i + 2) * NC + j]);
        m3 = fmaxf(m3, hpo[(size_t)(i + 3) * NC + j]);
    }
    float m = fmaxf(fmaxf(m0, m1), fmaxf(m2, m3));
    #pragma unroll 8
    for (int b = 0; b < BB; b++)
        out[b * NC + j] = g_flat[b * NC + j] * m;
}

// ---------------- launcher ----------------
extern "C" void kernel_launch(void* const* d_in, const int* in_sizes, int n_in,
                              void* d_out, int out_size)
{
    const float* gos  = (const float*)d_in[0];
    const float* expx = (const float*)d_in[1];
    const float* W1   = (const float*)d_in[2];
    const float* b1   = (const float*)d_in[3];
    const float* W2   = (const float*)d_in[4];
    const float* b2   = (const float*)d_in[5];
    const float* hpo  = (const float*)d_in[6];
    float* out = (float*)d_out;

    cudaFuncSetAttribute(gemm_hmma, cudaFuncAttributeMaxDynamicSharedMemorySize, 55296);

    __nv_bfloat16 *a1h, *a1l, *b1h, *b1l, *xh, *xl, *b2h, *b2l;
    float *p1, *p2;
    cudaGetSymbolAddress((void**)&a1h, g_A1h);
    cudaGetSymbolAddress((void**)&a1l, g_A1l);
    cudaGetSymbolAddress((void**)&b1h, g_B1h);
    cudaGetSymbolAddress((void**)&b1l, g_B1l);
    cudaGetSymbolAddress((void**)&p1,  g_part1);
    cudaGetSymbolAddress((void**)&xh,  g_xh);
    cudaGetSymbolAddress((void**)&xl,  g_xl);
    cudaGetSymbolAddress((void**)&b2h, g_B2h);
    cudaGetSymbolAddress((void**)&b2l, g_B2l);
    cudaGetSymbolAddress((void**)&p2,  g_part2);

    // convert inputs to bf16 hi/lo
    convA<<<(BB * INS + 255) / 256, 256>>>(gos);
    convBT<<<dim3((INS + 31) / 32, (HID + 31) / 32), dim3(32, 8)>>>(W1, INS, HID, b1h, b1l, INS);
    convBT<<<dim3((KXP + 31) / 32, (NC + 31) / 32), dim3(32, 8)>>>(W2, KX, NC, b2h, b2l, KXP);

    // GEMM1: (64 x 10000) @ (10000 x 1500), split-K 23
    gemm_hmma<<<dim3(12, S1), 256, 55296>>>(a1h, a1l, INS, b1h, b1l, INS, p1, HID, INS, SPAN1);

    fuse1<<<(BB * KXP) / 256, 256>>>(b1, expx);

    // GEMM2: (64 x 1664pad) @ (1664 x 2048), split-K 13
    gemm_hmma<<<dim3(16, S2), 256, 55296>>>(xh, xl, KXP, b2h, b2l, KXP, p2, NC, KXP, SPAN2);

    fuse2<<<(BB * NC) / 256, 256>>>(b2);
    colmax_mul<<<NC / 256, 256>>>(hpo, out);
}

// round 4
// speedup vs baseline: 1.2841x; 1.2841x over previous
#include <cuda_runtime.h>
#include <cuda_bf16.h>
#include <math.h>
#include <stdint.h>

#define BB    64
#define INS   10000
#define EXPS  53
#define HID   1500
#define NC    2048
#define KX    1553
#define KXP   1664          // KX zero-padded to multiple of 128
#define S1    23
#define SPAN1 448           // 23*448 = 10304 >= 10000
#define S2    13
#define SPAN2 128           // 13*128 = 1664 exactly

#define STAGE_BYTES 55296   // one pipeline stage (Ah,Al,Bh,Bl padded tiles)

// ---------------- device scratch (no allocs allowed) ----------------
__device__ __align__(16) __nv_bfloat16 g_A1h[BB * INS], g_A1l[BB * INS];
__device__ __align__(16) __nv_bfloat16 g_B1h[HID * INS], g_B1l[HID * INS];
__device__ float g_part1[S1][BB][HID];
__device__ __align__(16) __nv_bfloat16 g_xh[BB * KXP], g_xl[BB * KXP];
__device__ __align__(16) __nv_bfloat16 g_B2h[NC * KXP], g_B2l[NC * KXP];
__device__ float g_part2[S2][BB][NC];
__device__ float g_flat[BB * NC];

__device__ __forceinline__ uint32_t smem_u32(const void* p) {
    uint32_t a;
    asm("{ .reg .u64 t; cvta.to.shared.u64 t, %1; cvt.u32.u64 %0, t; }" : "=r"(a) : "l"(p));
    return a;
}
#define LDX4(r, addr)                                                        \
    asm volatile("ldmatrix.sync.aligned.m8n8.x4.shared.b16 {%0,%1,%2,%3}, [%4];" \
        : "=r"((r)[0]), "=r"((r)[1]), "=r"((r)[2]), "=r"((r)[3]) : "r"(addr))
#define MMA16816(d, a, b)                                                    \
    asm volatile("mma.sync.aligned.m16n8k16.row.col.f32.bf16.bf16.f32 "      \
        "{%0,%1,%2,%3}, {%4,%5,%6,%7}, {%8,%9}, {%0,%1,%2,%3};"              \
        : "+f"((d)[0]), "+f"((d)[1]), "+f"((d)[2]), "+f"((d)[3])             \
        : "r"((a)[0]), "r"((a)[1]), "r"((a)[2]), "r"((a)[3]),                \
          "r"((b)[0]), "r"((b)[1]))
__device__ __forceinline__ void cp16(uint32_t dst, const void* src, int src_bytes) {
    asm volatile("cp.async.cg.shared.global [%0], [%1], 16, %2;"
                 :: "r"(dst), "l"(src), "r"(src_bytes) : "memory");
}
#define CP_COMMIT()  asm volatile("cp.async.commit_group;" ::: "memory")
#define CP_WAIT(n)   asm volatile("cp.async.wait_group %0;" :: "n"(n) : "memory")

// ---------------------------------------------------------------------------
// HMMA split-K GEMM, cp.async double-buffered.
// Block: 256 thr, tile M=64 x N=128 x Kchunk=64. Warp = 32(M) x 32(N).
// part[split][m][n] = sum_{k in split} A[m,k] * B[n,k]
// Stage layout (bytes): Ah@0 (64x72), Al@9216, Bh@18432 (128x72), Bl@36864.
// ---------------------------------------------------------------------------
__global__ __launch_bounds__(256) void gemm_hmma(
    const __nv_bfloat16* __restrict__ Ah, const __nv_bfloat16* __restrict__ Al, int lda,
    const __nv_bfloat16* __restrict__ Bh, const __nv_bfloat16* __restrict__ Bl, int ldb,
    float* __restrict__ part, int N, int K, int span)
{
    extern __shared__ __align__(16) char sm[];
    const int tid = threadIdx.x, lane = tid & 31, w = tid >> 5;
    const int n0 = blockIdx.x * 128;
    const int k0 = blockIdx.y * span;
    const int kend = min(k0 + span, K);
    const int nch = (kend - k0 + 63) >> 6;

    const uint32_t sbase = smem_u32(sm);

    // per-thread staging map: 12 granules = 4 A + 8 B
    // A granules: i in {tid, tid+256, tid+512, tid+768}
    // B granules: j in {tid, ..., tid+1792}
    const int wm = (w & 1) * 32;
    const int wn = (w >> 1) * 32;

    float acc[2][4][4];
    #pragma unroll
    for (int i = 0; i < 2; i++)
        #pragma unroll
        for (int j = 0; j < 4; j++)
            #pragma unroll
            for (int e = 0; e < 4; e++) acc[i][j][e] = 0.f;

    const int aRow = lane & 15, aCol = (lane >> 4) * 8;
    const int bRow = (lane & 7) + (lane >> 4) * 8, bCol = ((lane >> 3) & 1) * 8;

    // ---- stage loader (cp.async, ZFILL for OOB) ----
    auto stage = [&](int c) {
        const int kt = k0 + c * 64;
        const uint32_t sb = sbase + (uint32_t)(c & 1) * STAGE_BYTES;
        #pragma unroll
        for (int u = 0; u < 4; u++) {            // A: 1024 granules
            int i = tid + u * 256;
            int isL = i >> 9;                     // 0 = hi, 1 = lo
            int idx = i & 511, r = idx >> 3, g = idx & 7;
            int gk = kt + g * 8;
            const __nv_bfloat16* src = (isL ? Al : Ah) + (size_t)r * lda + gk;
            int ok = (gk + 8 <= kend) ? 16 : 0;
            uint32_t dst = sb + (isL ? 9216u : 0u) + (uint32_t)(r * 72 + g * 8) * 2u;
            cp16(dst, src, ok);
        }
        #pragma unroll
        for (int u = 0; u < 8; u++) {            // B: 2048 granules
            int j = tid + u * 256;
            int isL = j >> 10;
            int idx = j & 1023, r = idx >> 3, g = idx & 7;
            int gk = kt + g * 8;
            int n = n0 + r;
            const __nv_bfloat16* src = (isL ? Bl : Bh) + (size_t)n * ldb + gk;
            int ok = (n < N && gk + 8 <= kend) ? 16 : 0;
            uint32_t dst = sb + (isL ? 36864u : 18432u) + (uint32_t)(r * 72 + g * 8) * 2u;
            cp16(dst, src, ok);
        }
        CP_COMMIT();
    };

    stage(0);

    for (int c = 0; c < nch; c++) {
        __syncthreads();                 // buffer (c+1)&1 free (compute c-1 done)
        if (c + 1 < nch) {
            stage(c + 1);
            CP_WAIT(1);                  // chunk c complete, c+1 in flight
        } else {
            CP_WAIT(0);
        }
        __syncthreads();                 // chunk c visible to all warps

        const uint32_t sb = sbase + (uint32_t)(c & 1) * STAGE_BYTES;
        #pragma unroll
        for (int ks = 0; ks < 4; ks++) {
            const int kk = ks * 16;
            uint32_t ah[2][4], al[2][4], bh[2][4], bl[2][4];
            #pragma unroll
            for (int mi = 0; mi < 2; mi++) {
                uint32_t ad = sb + ((wm + mi * 16 + aRow) * 72 + kk + aCol) * 2;
                LDX4(ah[mi], ad);
                LDX4(al[mi], ad + 9216u);
            }
            #pragma unroll
            for (int p = 0; p < 2; p++) {
                uint32_t bd = sb + 18432u + ((wn + p * 16 + bRow) * 72 + kk + bCol) * 2;
                LDX4(bh[p], bd);
                LDX4(bl[p], bd + 18432u);
            }
            #pragma unroll
            for (int mi = 0; mi < 2; mi++)
                #pragma unroll
                for (int ni = 0; ni < 4; ni++) {
                    uint32_t* bhp = &bh[ni >> 1][(ni & 1) * 2];
                    uint32_t* blp = &bl[ni >> 1][(ni & 1) * 2];
                    MMA16816(acc[mi][ni], ah[mi], bhp);
                    MMA16816(acc[mi][ni], ah[mi], blp);
                    MMA16816(acc[mi][ni], al[mi], bhp);
                }
        }
    }

    // ---- epilogue: write split-K partials
    float* pb = part + (size_t)blockIdx.y * 64 * N;
    #pragma unroll
    for (int mi = 0; mi < 2; mi++)
        #pragma unroll
        for (int ni = 0; ni < 4; ni++) {
            int r0 = wm + mi * 16 + (lane >> 2);
            int cc = n0 + wn + ni * 8 + (lane & 3) * 2;
            if (cc < N) {
                pb[r0 * N + cc] = acc[mi][ni][0];
                pb[(r0 + 8) * N + cc] = acc[mi][ni][2];
            }
            if (cc + 1 < N) {
                pb[r0 * N + cc + 1] = acc[mi][ni][1];
                pb[(r0 + 8) * N + cc + 1] = acc[mi][ni][3];
            }
        }
}

// ---------------- conversion kernels ----------------
__global__ void convA(const float* __restrict__ A)
{
    int idx = blockIdx.x * 256 + threadIdx.x;
    if (idx >= BB * INS) return;
    float v = A[idx];
    __nv_bfloat16 h = __float2bfloat16(v);
    g_A1h[idx] = h;
    g_A1l[idx] = __float2bfloat16(v - __bfloat162float(h));
}

// W [K][N] fp32 -> Bh/Bl [N][Kpad] bf16 (transposed, K-contiguous, zero-padded)
__global__ void convBT(const float* __restrict__ W, int K, int Nn,
                       __nv_bfloat16* __restrict__ Bh, __nv_bfloat16* __restrict__ Bl, int Kpad)
{
    __shared__ float t[32][33];
    int k0 = blockIdx.x * 32, n0 = blockIdx.y * 32;
    int tx = threadIdx.x, ty = threadIdx.y;
    #pragma unroll
    for (int j = 0; j < 4; j++) {
        int k = k0 + ty + j * 8, n = n0 + tx;
        t[ty + j * 8][tx] = (k < K && n < Nn) ? W[(size_t)k * Nn + n] : 0.f;
    }
    __syncthreads();
    #pragma unroll
    for (int j = 0; j < 4; j++) {
        int n = n0 + ty + j * 8, k = k0 + tx;
        if (n < Nn && k < Kpad) {
            float v = t[tx][ty + j * 8];
            __nv_bfloat16 h = __float2bfloat16(v);
            Bh[(size_t)n * Kpad + k] = h;
            Bl[(size_t)n * Kpad + k] = __float2bfloat16(v - __bfloat162float(h));
        }
    }
}

// ---------------- fused epilogues ----------------
__global__ void fuse1(const float* __restrict__ b1, const float* __restrict__ expx)
{
    int idx = blockIdx.x * 256 + threadIdx.x;
    if (idx >= BB * KXP) return;
    int b = idx / KXP, n = idx - b * KXP;
    float v;
    if (n < HID) {
        float s = b1[n];
        #pragma unroll
        for (int p = 0; p < S1; p++) s += g_part1[p][b][n];
        v = 0.5f * s * (1.f + erff(s * 0.70710678118654752f));
    } else if (n < KX) {
        v = expx[b * EXPS + (n - HID)];
    } else {
        v = 0.f;
    }
    __nv_bfloat16 h = __float2bfloat16(v);
    g_xh[idx] = h;
    g_xl[idx] = __float2bfloat16(v - __bfloat162float(h));
}

__global__ void fuse2(const float* __restrict__ b2)
{
    int idx = blockIdx.x * 256 + threadIdx.x;
    if (idx >= BB * NC) return;
    int b = idx >> 11, n = idx & (NC - 1);
    float s = b2[n];
    #pragma unroll
    for (int p = 0; p < S2; p++) s += g_part2[p][b][n];
    g_flat[idx] = 1.f / (1.f + expf(-s));
}

// out[b,j] = flat[b,j] * max_i M[i,j]   (exact: flat>0, M>=0)
__global__ void colmax_mul(const float* __restrict__ hpo, float* __restrict__ out)
{
    int j = blockIdx.x * 256 + threadIdx.x;
    float m0 = hpo[j], m1 = hpo[NC + j], m2 = hpo[2 * NC + j], m3 = hpo[3 * NC + j];
    #pragma unroll 4
    for (int i = 4; i < NC; i += 4) {
        m0 = fmaxf(m0, hpo[(size_t)i * NC + j]);
        m1 = fmaxf(m1, hpo[(size_t)(i + 1) * NC + j]);
        m2 = fmaxf(m2, hpo[(size_t)(i + 2) * NC + j]);
        m3 = fmaxf(m3, hpo[(size_t)(i + 3) * NC + j]);
    }
    float m = fmaxf(fmaxf(m0, m1), fmaxf(m2, m3));
    #pragma unroll 8
    for (int b = 0; b < BB; b++)
        out[b * NC + j] = g_flat[b * NC + j] * m;
}

// ---------------- launcher ----------------
extern "C" void kernel_launch(void* const* d_in, const int* in_sizes, int n_in,
                              void* d_out, int out_size)
{
    const float* gos  = (const float*)d_in[0];
    const float* expx = (const float*)d_in[1];
    const float* W1   = (const float*)d_in[2];
    const float* b1   = (const float*)d_in[3];
    const float* W2   = (const float*)d_in[4];
    const float* b2   = (const float*)d_in[5];
    const float* hpo  = (const float*)d_in[6];
    float* out = (float*)d_out;

    cudaFuncSetAttribute(gemm_hmma, cudaFuncAttributeMaxDynamicSharedMemorySize,
                         2 * STAGE_BYTES);

    __nv_bfloat16 *a1h, *a1l, *b1h, *b1l, *xh, *xl, *b2h, *b2l;
    float *p1, *p2;
    cudaGetSymbolAddress((void**)&a1h, g_A1h);
    cudaGetSymbolAddress((void**)&a1l, g_A1l);
    cudaGetSymbolAddress((void**)&b1h, g_B1h);
    cudaGetSymbolAddress((void**)&b1l, g_B1l);
    cudaGetSymbolAddress((void**)&p1,  g_part1);
    cudaGetSymbolAddress((void**)&xh,  g_xh);
    cudaGetSymbolAddress((void**)&xl,  g_xl);
    cudaGetSymbolAddress((void**)&b2h, g_B2h);
    cudaGetSymbolAddress((void**)&b2l, g_B2l);
    cudaGetSymbolAddress((void**)&p2,  g_part2);

    convA<<<(BB * INS + 255) / 256, 256>>>(gos);
    convBT<<<dim3((INS + 31) / 32, (HID + 31) / 32), dim3(32, 8)>>>(W1, INS, HID, b1h, b1l, INS);
    convBT<<<dim3((KXP + 31) / 32, (NC + 31) / 32), dim3(32, 8)>>>(W2, KX, NC, b2h, b2l, KXP);

    // GEMM1: (64 x 10000) @ (10000 x 1500), split-K 23
    gemm_hmma<<<dim3(12, S1), 256, 2 * STAGE_BYTES>>>(a1h, a1l, INS, b1h, b1l, INS, p1, HID, INS, SPAN1);

    fuse1<<<(BB * KXP) / 256, 256>>>(b1, expx);

    // GEMM2: (64 x 1664pad) @ (1664 x 2048), split-K 13
    gemm_hmma<<<dim3(16, S2), 256, 2 * STAGE_BYTES>>>(xh, xl, KXP, b2h, b2l, KXP, p2, NC, KXP, SPAN2);

    fuse2<<<(BB * NC) / 256, 256>>>(b2);
    colmax_mul<<<NC / 256, 256>>>(hpo, out);
}

// round 5
// speedup vs baseline: 1.5403x; 1.1995x over previous
#include <cuda_runtime.h>
#include <cuda_bf16.h>
#include <math.h>
#include <stdint.h>

#define BB    64
#define INS   10000
#define EXPS  53
#define HID   1500
#define NC    2048
#define KX    1553
#define KXP   1664
#define S1    23
#define SPAN1 448
#define S2    13
#define SPAN2 128

// stage layout (bytes): Ah@0 (64x72 bf16), Al@9216, Bh@18432 (64k x 136n bf16), Bl@35840
#define OFF_AL 9216
#define OFF_BH 18432
#define OFF_BL 35840
#define STAGE  53248

// ---------------- device scratch ----------------
__device__ __align__(16) __nv_bfloat16 g_A1h[BB * INS], g_A1l[BB * INS];
__device__ float g_part1[S1][BB][HID];
__device__ __align__(16) __nv_bfloat16 g_xh[BB * KXP], g_xl[BB * KXP];
__device__ float g_part2[S2][BB][NC];
__device__ float g_flat[BB * NC];

__device__ __forceinline__ uint32_t smem_u32(const void* p) {
    uint32_t a;
    asm("{ .reg .u64 t; cvta.to.shared.u64 t, %1; cvt.u32.u64 %0, t; }" : "=r"(a) : "l"(p));
    return a;
}
#define LDX4(r, addr)                                                        \
    asm volatile("ldmatrix.sync.aligned.m8n8.x4.shared.b16 {%0,%1,%2,%3}, [%4];" \
        : "=r"((r)[0]), "=r"((r)[1]), "=r"((r)[2]), "=r"((r)[3]) : "r"(addr))
#define LDX4T(r, addr)                                                       \
    asm volatile("ldmatrix.sync.aligned.m8n8.x4.trans.shared.b16 {%0,%1,%2,%3}, [%4];" \
        : "=r"((r)[0]), "=r"((r)[1]), "=r"((r)[2]), "=r"((r)[3]) : "r"(addr))
#define MMA16816(d, a, b)                                                    \
    asm volatile("mma.sync.aligned.m16n8k16.row.col.f32.bf16.bf16.f32 "      \
        "{%0,%1,%2,%3}, {%4,%5,%6,%7}, {%8,%9}, {%0,%1,%2,%3};"              \
        : "+f"((d)[0]), "+f"((d)[1]), "+f"((d)[2]), "+f"((d)[3])             \
        : "r"((a)[0]), "r"((a)[1]), "r"((a)[2]), "r"((a)[3]),                \
          "r"((b)[0]), "r"((b)[1]))
__device__ __forceinline__ void cp16(uint32_t dst, const void* src, int src_bytes) {
    asm volatile("cp.async.cg.shared.global [%0], [%1], 16, %2;"
                 :: "r"(dst), "l"(src), "r"(src_bytes) : "memory");
}
#define CP_COMMIT()  asm volatile("cp.async.commit_group;" ::: "memory")
#define CP_WAIT0()   asm volatile("cp.async.wait_group 0;" ::: "memory")

// ---------------------------------------------------------------------------
// HMMA split-K GEMM. A: preconverted bf16 hi/lo (cp.async, [m][k] smem).
// B: raw fp32 weights [K][N], LDG->reg buffer->convert->STS [k][n] smem,
// fragments via ldmatrix.trans. part[split][m][n] = sum_k A[m,k]*W[k,n].
// Block 256 thr, tile M=64 x N=128 x Kchunk=64; warp = 32(M) x 32(N).
// ---------------------------------------------------------------------------
__global__ __launch_bounds__(256, 2) void gemm_hmma(
    const __nv_bfloat16* __restrict__ Ah, const __nv_bfloat16* __restrict__ Al,
    int KA,                               // A buffer K extent (= lda)
    const float* __restrict__ W, int KB,  // raw weights [KB][Nn]
    float* __restrict__ part, int Nn, int span)
{
    extern __shared__ __align__(16) char sm[];
    const int tid = threadIdx.x, lane = tid & 31, w = tid >> 5;
    const int n0 = blockIdx.x * 128;
    const int k0 = blockIdx.y * span;
    const int kendA = min(k0 + span, KA);
    const int kendB = min(k0 + span, KB);
    const int nch = (kendA - k0 + 63) >> 6;

    const uint32_t sbase = smem_u32(sm);
    const int wm = (w & 1) * 32;
    const int wn = (w >> 1) * 32;

    float acc[2][4][4];
    #pragma unroll
    for (int i = 0; i < 2; i++)
        #pragma unroll
        for (int j = 0; j < 4; j++)
            #pragma unroll
            for (int e = 0; e < 4; e++) acc[i][j][e] = 0.f;

    const int aRow = lane & 15, aCol = (lane >> 4) * 8;
    const int bRowT = lane & 15, bColT = (lane >> 4) * 8;
    const int bn = n0 + lane * 4;          // this thread's B column (float4)
    const bool bnOK = (bn < Nn);

    float4 buf[8];

    auto ldgB = [&](int c) {
        const int kt = k0 + c * 64;
        #pragma unroll
        for (int u = 0; u < 8; u++) {
            int gk = kt + w + u * 8;
            if (gk < kendB && bnOK)
                buf[u] = *(const float4*)(W + (size_t)gk * Nn + bn);
            else
                buf[u] = make_float4(0.f, 0.f, 0.f, 0.f);
        }
    };
    auto stsB = [&](int c) {
        char* sb = sm + (c & 1) * STAGE;
        #pragma unroll
        for (int u = 0; u < 8; u++) {
            float4 v = buf[u];
            __nv_bfloat162 h0 = __floats2bfloat162_rn(v.x, v.y);
            __nv_bfloat162 h1 = __floats2bfloat162_rn(v.z, v.w);
            float lx = v.x - __bfloat162float(h0.x);
            float ly = v.y - __bfloat162float(h0.y);
            float lz = v.z - __bfloat162float(h1.x);
            float lw = v.w - __bfloat162float(h1.y);
            __nv_bfloat162 l0 = __floats2bfloat162_rn(lx, ly);
            __nv_bfloat162 l1 = __floats2bfloat162_rn(lz, lw);
            int rowOff = (w + u * 8) * 272 + lane * 8;
            *(uint2*)(sb + OFF_BH + rowOff) =
                make_uint2(*(uint32_t*)&h0, *(uint32_t*)&h1);
            *(uint2*)(sb + OFF_BL + rowOff) =
                make_uint2(*(uint32_t*)&l0, *(uint32_t*)&l1);
        }
    };
    auto cpA = [&](int c) {
        const int kt = k0 + c * 64;
        const uint32_t sb = sbase + (uint32_t)(c & 1) * STAGE;
        #pragma unroll
        for (int u = 0; u < 4; u++) {          // 1024 granules / 256 thr
            int i = tid + u * 256;
            int isL = i >> 9;
            int idx = i & 511, r = idx >> 3, g = idx & 7;
            int gk = kt + g * 8;
            const __nv_bfloat16* src = (isL ? Al : Ah) + (size_t)r * KA + gk;
            int ok = (gk + 8 <= kendA) ? 16 : 0;
            cp16(sb + (isL ? OFF_AL : 0u) + (uint32_t)(r * 72 + g * 8) * 2u, src, ok);
        }
        CP_COMMIT();
    };

    ldgB(0);
    cpA(0);

    for (int c = 0; c < nch; c++) {
        stsB(c);                   // buf (c&1): last MMA-read was chunk c-2, fenced
        CP_WAIT0();                // A(c) landed
        __syncthreads();           // stage c visible to all
        if (c + 1 < nch) {
            ldgB(c + 1);           // overlaps MMA below
            cpA(c + 1);
        }
        const uint32_t sb = sbase + (uint32_t)(c & 1) * STAGE;
        #pragma unroll
        for (int ks = 0; ks < 4; ks++) {
            const int kk = ks * 16;
            uint32_t ah[2][4], al[2][4], bh[2][4], bl[2][4];
            #pragma unroll
            for (int mi = 0; mi < 2; mi++) {
                uint32_t ad = sb + ((wm + mi * 16 + aRow) * 72 + kk + aCol) * 2;
                LDX4(ah[mi], ad);
                LDX4(al[mi], ad + OFF_AL);
            }
            #pragma unroll
            for (int p = 0; p < 2; p++) {
                uint32_t bd = sb + OFF_BH + (kk + bRowT) * 272
                            + (wn + p * 16 + bColT) * 2;
                LDX4T(bh[p], bd);
                LDX4T(bl[p], bd + (OFF_BL - OFF_BH));
            }
            #pragma unroll
            for (int mi = 0; mi < 2; mi++)
                #pragma unroll
                for (int ni = 0; ni < 4; ni++) {
                    uint32_t* bhp = &bh[ni >> 1][(ni & 1) * 2];
                    uint32_t* blp = &bl[ni >> 1][(ni & 1) * 2];
                    MMA16816(acc[mi][ni], ah[mi], bhp);
                    MMA16816(acc[mi][ni], ah[mi], blp);
                    MMA16816(acc[mi][ni], al[mi], bhp);
                }
        }
        __syncthreads();           // MMA(c) done before next stsB into buf (c+1)&1
    }

    float* pb = part + (size_t)blockIdx.y * 64 * Nn;
    #pragma unroll
    for (int mi = 0; mi < 2; mi++)
        #pragma unroll
        for (int ni = 0; ni < 4; ni++) {
            int r0 = wm + mi * 16 + (lane >> 2);
            int cc = n0 + wn + ni * 8 + (lane & 3) * 2;
            if (cc < Nn) {
                pb[r0 * Nn + cc] = acc[mi][ni][0];
                pb[(r0 + 8) * Nn + cc] = acc[mi][ni][2];
            }
            if (cc + 1 < Nn) {
                pb[r0 * Nn + cc + 1] = acc[mi][ni][1];
                pb[(r0 + 8) * Nn + cc + 1] = acc[mi][ni][3];
            }
        }
}

// ---------------- small kernels ----------------
__global__ void convA(const float* __restrict__ A)
{
    int idx = blockIdx.x * 256 + threadIdx.x;
    if (idx >= BB * INS) return;
    float v = A[idx];
    __nv_bfloat16 h = __float2bfloat16(v);
    g_A1h[idx] = h;
    g_A1l[idx] = __float2bfloat16(v - __bfloat162float(h));
}

__global__ void fuse1(const float* __restrict__ b1, const float* __restrict__ expx)
{
    int idx = blockIdx.x * 256 + threadIdx.x;
    if (idx >= BB * KXP) return;
    int b = idx / KXP, n = idx - b * KXP;
    float v;
    if (n < HID) {
        float s = b1[n];
        #pragma unroll
        for (int p = 0; p < S1; p++) s += g_part1[p][b][n];
        v = 0.5f * s * (1.f + erff(s * 0.70710678118654752f));
    } else if (n < KX) {
        v = expx[b * EXPS + (n - HID)];
    } else {
        v = 0.f;
    }
    __nv_bfloat16 h = __float2bfloat16(v);
    g_xh[idx] = h;
    g_xl[idx] = __float2bfloat16(v - __bfloat162float(h));
}

__global__ void fuse2(const float* __restrict__ b2)
{
    int idx = blockIdx.x * 256 + threadIdx.x;
    if (idx >= BB * NC) return;
    int b = idx >> 11, n = idx & (NC - 1);
    float s = b2[n];
    #pragma unroll
    for (int p = 0; p < S2; p++) s += g_part2[p][b][n];
    g_flat[idx] = 1.f / (1.f + expf(-s));
}

// out[b,j] = flat[b,j] * max_i M[i,j]   (exact: flat>0, M>=0)
__global__ void colmax_mul(const float* __restrict__ hpo, float* __restrict__ out)
{
    int j = blockIdx.x * 256 + threadIdx.x;
    float m0 = hpo[j], m1 = hpo[NC + j], m2 = hpo[2 * NC + j], m3 = hpo[3 * NC + j];
    #pragma unroll 4
    for (int i = 4; i < NC; i += 4) {
        m0 = fmaxf(m0, hpo[(size_t)i * NC + j]);
        m1 = fmaxf(m1, hpo[(size_t)(i + 1) * NC + j]);
        m2 = fmaxf(m2, hpo[(size_t)(i + 2) * NC + j]);
        m3 = fmaxf(m3, hpo[(size_t)(i + 3) * NC + j]);
    }
    float m = fmaxf(fmaxf(m0, m1), fmaxf(m2, m3));
    #pragma unroll 8
    for (int b = 0; b < BB; b++)
        out[b * NC + j] = g_flat[b * NC + j] * m;
}

// ---------------- launcher ----------------
extern "C" void kernel_launch(void* const* d_in, const int* in_sizes, int n_in,
                              void* d_out, int out_size)
{
    const float* gos  = (const float*)d_in[0];
    const float* expx = (const float*)d_in[1];
    const float* W1   = (const float*)d_in[2];
    const float* b1   = (const float*)d_in[3];
    const float* W2   = (const float*)d_in[4];
    const float* b2   = (const float*)d_in[5];
    const float* hpo  = (const float*)d_in[6];
    float* out = (float*)d_out;

    cudaFuncSetAttribute(gemm_hmma, cudaFuncAttributeMaxDynamicSharedMemorySize,
                         2 * STAGE);

    __nv_bfloat16 *a1h, *a1l, *xh, *xl;
    float *p1, *p2;
    cudaGetSymbolAddress((void**)&a1h, g_A1h);
    cudaGetSymbolAddress((void**)&a1l, g_A1l);
    cudaGetSymbolAddress((void**)&p1,  g_part1);
    cudaGetSymbolAddress((void**)&xh,  g_xh);
    cudaGetSymbolAddress((void**)&xl,  g_xl);
    cudaGetSymbolAddress((void**)&p2,  g_part2);

    convA<<<(BB * INS + 255) / 256, 256>>>(gos);

    // GEMM1: (64 x 10000) @ W1(10000 x 1500), split-K 23, direct fp32 W reads
    gemm_hmma<<<dim3(12, S1), 256, 2 * STAGE>>>(a1h, a1l, INS, W1, INS, p1, HID, SPAN1);

    fuse1<<<(BB * KXP) / 256, 256>>>(b1, expx);

    // GEMM2: (64 x 1553/1664pad) @ W2(1553 x 2048), split-K 13
    gemm_hmma<<<dim3(16, S2), 256, 2 * STAGE>>>(xh, xl, KXP, W2, KX, p2, NC, SPAN2);

    fuse2<<<(BB * NC) / 256, 256>>>(b2);
    colmax_mul<<<NC / 256, 256>>>(hpo, out);
}

// round 6
// speedup vs baseline: 3.5700x; 2.3177x over previous
#include <cuda_runtime.h>
#include <cuda_bf16.h>
#include <math.h>
#include <stdint.h>

#define BB    64
#define INS   10000
#define EXPS  53
#define HID   1500
#define NC    2048
#define KX    1553
#define KXP   1664
#define S1    12
#define SPAN1 840           // 12*840 = 10080 >= 10000 (mult of 8)
#define S2    9
#define SPAN2 192           // 9*192 = 1728 >= 1664

// GEMM smem layout (bytes):
// stage s (s=0,1) at s*STG: Ah@0 (64x72 bf16 =9216), Al@9216, Bf32@18432 (64x132 f32 =33792)
// convert buffers (single): Ch@104448 (64x136 bf16 =17408), Cl@121856. total 139264.
#define OFF_AL  9216
#define OFF_B   18432
#define STG     52224
#define OFF_CH  104448
#define OFF_CL  121856
#define SMEM_T  139264

#define CONVA_BLKS 2500     // 2500*256 = 640000 = BB*INS exactly

// ---------------- device scratch ----------------
__device__ __align__(16) __nv_bfloat16 g_A1h[BB * INS], g_A1l[BB * INS];
__device__ float g_part1[S1][BB][HID];
__device__ __align__(16) __nv_bfloat16 g_xh[BB * KXP], g_xl[BB * KXP];
__device__ float g_part2[S2][BB][NC];
__device__ float g_cmax[32][NC];

__device__ __forceinline__ uint32_t smem_u32(const void* p) {
    uint32_t a;
    asm("{ .reg .u64 t; cvta.to.shared.u64 t, %1; cvt.u32.u64 %0, t; }" : "=r"(a) : "l"(p));
    return a;
}
#define LDX4(r, addr)                                                        \
    asm volatile("ldmatrix.sync.aligned.m8n8.x4.shared.b16 {%0,%1,%2,%3}, [%4];" \
        : "=r"((r)[0]), "=r"((r)[1]), "=r"((r)[2]), "=r"((r)[3]) : "r"(addr))
#define LDX4T(r, addr)                                                       \
    asm volatile("ldmatrix.sync.aligned.m8n8.x4.trans.shared.b16 {%0,%1,%2,%3}, [%4];" \
        : "=r"((r)[0]), "=r"((r)[1]), "=r"((r)[2]), "=r"((r)[3]) : "r"(addr))
#define MMA16816(d, a, b)                                                    \
    asm volatile("mma.sync.aligned.m16n8k16.row.col.f32.bf16.bf16.f32 "      \
        "{%0,%1,%2,%3}, {%4,%5,%6,%7}, {%8,%9}, {%0,%1,%2,%3};"              \
        : "+f"((d)[0]), "+f"((d)[1]), "+f"((d)[2]), "+f"((d)[3])             \
        : "r"((a)[0]), "r"((a)[1]), "r"((a)[2]), "r"((a)[3]),                \
          "r"((b)[0]), "r"((b)[1]))
__device__ __forceinline__ void cp16(uint32_t dst, const void* src, int src_bytes) {
    asm volatile("cp.async.cg.shared.global [%0], [%1], 16, %2;"
                 :: "r"(dst), "l"(src), "r"(src_bytes) : "memory");
}
#define CP_COMMIT()  asm volatile("cp.async.commit_group;" ::: "memory")
#define CP_WAIT(n)   asm volatile("cp.async.wait_group %0;" :: "n"(n) : "memory")

// ---------------------------------------------------------------------------
// HMMA split-K GEMM. A: preconverted bf16 hi/lo via cp.async ([m][k] smem).
// B: raw fp32 W [K][N] via cp.async into smem, converted smem->smem to bf16
// hi/lo [k][n] each chunk; fragments via ldmatrix(.trans).
// Tile M=64 x N=128 x Kchunk=64; 256 thr; warp = 32(M) x 32(N).
// ---------------------------------------------------------------------------
__global__ __launch_bounds__(256, 1) void gemm_hmma(
    const __nv_bfloat16* __restrict__ Ah, const __nv_bfloat16* __restrict__ Al,
    int KA, const float* __restrict__ W, int KB,
    float* __restrict__ part, int Nn, int span)
{
    extern __shared__ __align__(16) char sm[];
    const int tid = threadIdx.x, lane = tid & 31, w = tid >> 5;
    const int n0 = blockIdx.x * 128;
    const int k0 = blockIdx.y * span;
    const int kendA = min(k0 + span, KA);
    const int kendB = min(k0 + span, KB);
    const int nch = (kendA - k0 + 63) >> 6;
    const uint32_t sbase = smem_u32(sm);
    const int wm = (w & 1) * 32, wn = (w >> 1) * 32;

    float acc[2][4][4];
    #pragma unroll
    for (int i = 0; i < 2; i++)
        #pragma unroll
        for (int j = 0; j < 4; j++)
            #pragma unroll
            for (int e = 0; e < 4; e++) acc[i][j][e] = 0.f;

    const int aRow = lane & 15, aCol = (lane >> 4) * 8;
    const int bRowT = lane & 15, bColT = (lane >> 4) * 8;

    // convert-thread mapping: row = tid&63 (conflict-free LDS), seg = tid>>6
    const int cvR = tid & 63, cvS = tid >> 6;

    auto stage_cp = [&](int c) {
        const int kt = k0 + c * 64;
        const uint32_t sb = sbase + (uint32_t)(c & 1) * STG;
        #pragma unroll
        for (int u = 0; u < 4; u++) {                 // A: 1024 granules
            int i = tid + u * 256;
            int isL = i >> 9, idx = i & 511, r = idx >> 3, g = idx & 7;
            int gk = kt + g * 8;
            const __nv_bfloat16* src = (isL ? Al : Ah) + (size_t)r * KA + gk;
            int ok = (gk + 8 <= kendA) ? 16 : 0;
            cp16(sb + (isL ? OFF_AL : 0u) + (uint32_t)(r * 72 + g * 8) * 2u, src, ok);
        }
        #pragma unroll
        for (int u = 0; u < 8; u++) {                 // B fp32: 2048 granules
            int j = tid + u * 256;
            int r = j >> 5, g = j & 31;
            int gk = kt + r, n = n0 + g * 4;
            const float* src = W + (size_t)gk * Nn + n;
            int ok = (gk < kendB && n < Nn) ? 16 : 0;
            cp16(sb + OFF_B + (uint32_t)(r * 528 + g * 16), src, ok);
        }
        CP_COMMIT();
    };

    stage_cp(0);

    for (int c = 0; c < nch; c++) {
        if (c + 1 < nch) { stage_cp(c + 1); CP_WAIT(1); }
        else             { CP_WAIT(0); }
        __syncthreads();

        // ---- convert fp32 B tile (stage c) -> Ch/Cl bf16 hi/lo
        {
            const char* bs = sm + (c & 1) * STG + OFF_B + cvR * 528 + cvS * 128;
            char* ch = sm + OFF_CH + cvR * 272 + cvS * 64;
            char* cl = sm + OFF_CL + cvR * 272 + cvS * 64;
            #pragma unroll
            for (int i = 0; i < 8; i++) {
                float4 v = *(const float4*)(bs + i * 16);
                __nv_bfloat162 h0 = __floats2bfloat162_rn(v.x, v.y);
                __nv_bfloat162 h1 = __floats2bfloat162_rn(v.z, v.w);
                __nv_bfloat162 l0 = __floats2bfloat162_rn(
                    v.x - __bfloat162float(h0.x), v.y - __bfloat162float(h0.y));
                __nv_bfloat162 l1 = __floats2bfloat162_rn(
                    v.z - __bfloat162float(h1.x), v.w - __bfloat162float(h1.y));
                *(uint2*)(ch + i * 8) = make_uint2(*(uint32_t*)&h0, *(uint32_t*)&h1);
                *(uint2*)(cl + i * 8) = make_uint2(*(uint32_t*)&l0, *(uint32_t*)&l1);
            }
        }
        __syncthreads();

        const uint32_t sb = sbase + (uint32_t)(c & 1) * STG;
        #pragma unroll
        for (int ks = 0; ks < 4; ks++) {
            const int kk = ks * 16;
            uint32_t ah[2][4], al[2][4], bh[2][4], bl[2][4];
            #pragma unroll
            for (int mi = 0; mi < 2; mi++) {
                uint32_t ad = sb + ((wm + mi * 16 + aRow) * 72 + kk + aCol) * 2;
                LDX4(ah[mi], ad);
                LDX4(al[mi], ad + OFF_AL);
            }
            #pragma unroll
            for (int p = 0; p < 2; p++) {
                uint32_t bd = sbase + OFF_CH + (kk + bRowT) * 272
                            + (wn + p * 16 + bColT) * 2;
                LDX4T(bh[p], bd);
                LDX4T(bl[p], bd + (OFF_CL - OFF_CH));
            }
            #pragma unroll
            for (int mi = 0; mi < 2; mi++)
                #pragma unroll
                for (int ni = 0; ni < 4; ni++) {
                    uint32_t* bhp = &bh[ni >> 1][(ni & 1) * 2];
                    uint32_t* blp = &bl[ni >> 1][(ni & 1) * 2];
                    MMA16816(acc[mi][ni], ah[mi], bhp);
                    MMA16816(acc[mi][ni], ah[mi], blp);
                    MMA16816(acc[mi][ni], al[mi], bhp);
                }
        }
        __syncthreads();
    }

    float* pb = part + (size_t)blockIdx.y * 64 * Nn;
    #pragma unroll
    for (int mi = 0; mi < 2; mi++)
        #pragma unroll
        for (int ni = 0; ni < 4; ni++) {
            int r0 = wm + mi * 16 + (lane >> 2);
            int cc = n0 + wn + ni * 8 + (lane & 3) * 2;
            if (cc < Nn) {
                pb[r0 * Nn + cc] = acc[mi][ni][0];
                pb[(r0 + 8) * Nn + cc] = acc[mi][ni][2];
            }
            if (cc + 1 < Nn) {
                pb[r0 * Nn + cc + 1] = acc[mi][ni][1];
                pb[(r0 + 8) * Nn + cc + 1] = acc[mi][ni][3];
            }
        }
}

// ---------------- prep: convA + hpo column-max phase 1 ----------------
__global__ void prep(const float* __restrict__ A, const float* __restrict__ hpo)
{
    int bx = blockIdx.x;
    if (bx < CONVA_BLKS) {
        int idx = bx * 256 + threadIdx.x;          // exact: 2500*256 = BB*INS
        float v = A[idx];
        __nv_bfloat16 h = __float2bfloat16(v);
        g_A1h[idx] = h;
        g_A1l[idx] = __float2bfloat16(v - __bfloat162float(h));
    } else {
        int cb = bx - CONVA_BLKS;                  // 0..255
        int strip = cb >> 3;                       // 0..31 (64 rows each)
        int j = (cb & 7) * 256 + threadIdx.x;      // 0..2047
        const float* col = hpo + (size_t)(strip * 64) * NC + j;
        float m = col[0];
        #pragma unroll 8
        for (int i = 1; i < 64; i++)
            m = fmaxf(m, col[(size_t)i * NC]);
        g_cmax[strip][j] = m;
    }
}

// ---------------- fuse1: reduce partials + bias + GELU + concat + hi/lo ----
__global__ void fuse1(const float* __restrict__ b1, const float* __restrict__ expx)
{
    int idx = blockIdx.x * 256 + threadIdx.x;
    if (idx >= BB * KXP) return;
    int b = idx / KXP, n = idx - b * KXP;
    float v;
    if (n < HID) {
        float s = b1[n];
        #pragma unroll
        for (int p = 0; p < S1; p++) s += g_part1[p][b][n];
        v = 0.5f * s * (1.f + erff(s * 0.70710678118654752f));
    } else if (n < KX) {
        v = expx[b * EXPS + (n - HID)];
    } else {
        v = 0.f;
    }
    __nv_bfloat16 h = __float2bfloat16(v);
    g_xh[idx] = h;
    g_xl[idx] = __float2bfloat16(v - __bfloat162float(h));
}

// ---------------- final: reduce partials + sigmoid, colmax phase 2, multiply
// out[b,j] = sigmoid(sum + b2[j]) * max_i hpo[i,j]   (exact factorization)
__global__ void final_k(const float* __restrict__ b2, float* __restrict__ out)
{
    int j = blockIdx.x * 256 + threadIdx.x;
    int b = blockIdx.y;
    float m = g_cmax[0][j];
    #pragma unroll
    for (int p = 1; p < 32; p++) m = fmaxf(m, g_cmax[p][j]);
    float s = b2[j];
    #pragma unroll
    for (int p = 0; p < S2; p++) s += g_part2[p][b][j];
    out[b * NC + j] = m / (1.f + expf(-s));
}

// ---------------- launcher ----------------
extern "C" void kernel_launch(void* const* d_in, const int* in_sizes, int n_in,
                              void* d_out, int out_size)
{
    const float* gos  = (const float*)d_in[0];
    const float* expx = (const float*)d_in[1];
    const float* W1   = (const float*)d_in[2];
    const float* b1   = (const float*)d_in[3];
    const float* W2   = (const float*)d_in[4];
    const float* b2   = (const float*)d_in[5];
    const float* hpo  = (const float*)d_in[6];
    float* out = (float*)d_out;

    cudaFuncSetAttribute(gemm_hmma, cudaFuncAttributeMaxDynamicSharedMemorySize, SMEM_T);

    __nv_bfloat16 *a1h, *a1l, *xh, *xl;
    float *p1, *p2;
    cudaGetSymbolAddress((void**)&a1h, g_A1h);
    cudaGetSymbolAddress((void**)&a1l, g_A1l);
    cudaGetSymbolAddress((void**)&p1,  g_part1);
    cudaGetSymbolAddress((void**)&xh,  g_xh);
    cudaGetSymbolAddress((void**)&xl,  g_xl);
    cudaGetSymbolAddress((void**)&p2,  g_part2);

    // convA + hpo colmax strips
    prep<<<CONVA_BLKS + 256, 256>>>(gos, hpo);

    // GEMM1: (64 x 10000) @ W1(10000 x 1500), split-K 12, one wave (144 blocks)
    gemm_hmma<<<dim3(12, S1), 256, SMEM_T>>>(a1h, a1l, INS, W1, INS, p1, HID, SPAN1);

    fuse1<<<(BB * KXP) / 256, 256>>>(b1, expx);

    // GEMM2: (64 x 1553/1664pad) @ W2(1553 x 2048), split-K 9 (144 blocks)
    gemm_hmma<<<dim3(16, S2), 256, SMEM_T>>>(xh, xl, KXP, W2, KX, p2, NC, SPAN2);

    final_k<<<dim3(NC / 256, BB), 256>>>(b2, out);
}

// round 7
// speedup vs baseline: 3.6549x; 1.0238x over previous
#include <cuda_runtime.h>
#include <cuda_bf16.h>
#include <math.h>
#include <stdint.h>

#define BB    64
#define INS   10000
#define EXPS  53
#define HID   1500
#define NC    2048
#define KX    1553
#define KXP   1664
#define S1    24
#define SPAN1 424           // 24*424 = 10176 >= 10000, mult of 8
#define S2    18
#define SPAN2 96            // 18*96 = 1728 >= 1664, mult of 8

// stage: A f32 64 rows x stride 272B (17408) @0 ; B f32 64 rows x stride 528B (33792) @17408
#define OFF_B  17408
#define STG    51200
#define SMEM_T 102400       // 2 stages -> 2 CTAs/SM

// ---------------- device scratch ----------------
__device__ float g_part1[S1][BB][HID];
__device__ __align__(16) float g_x[BB * KXP];
__device__ float g_part2[S2][BB][NC];
__device__ float g_cmax[32][NC];

__device__ __forceinline__ uint32_t smem_u32(const void* p) {
    uint32_t a;
    asm("{ .reg .u64 t; cvta.to.shared.u64 t, %1; cvt.u32.u64 %0, t; }" : "=r"(a) : "l"(p));
    return a;
}
#define LDX4(r, addr)                                                        \
    asm volatile("ldmatrix.sync.aligned.m8n8.x4.shared.b16 {%0,%1,%2,%3}, [%4];" \
        : "=r"((r)[0]), "=r"((r)[1]), "=r"((r)[2]), "=r"((r)[3]) : "r"(addr))
#define LDX4T(r, addr)                                                       \
    asm volatile("ldmatrix.sync.aligned.m8n8.x4.trans.shared.b16 {%0,%1,%2,%3}, [%4];" \
        : "=r"((r)[0]), "=r"((r)[1]), "=r"((r)[2]), "=r"((r)[3]) : "r"(addr))
#define MMA16816(d, a, b)                                                    \
    asm volatile("mma.sync.aligned.m16n8k16.row.col.f32.bf16.bf16.f32 "      \
        "{%0,%1,%2,%3}, {%4,%5,%6,%7}, {%8,%9}, {%0,%1,%2,%3};"              \
        : "+f"((d)[0]), "+f"((d)[1]), "+f"((d)[2]), "+f"((d)[3])             \
        : "r"((a)[0]), "r"((a)[1]), "r"((a)[2]), "r"((a)[3]),                \
          "r"((b)[0]), "r"((b)[1]))
__device__ __forceinline__ void cp16(uint32_t dst, const void* src, int src_bytes) {
    asm volatile("cp.async.cg.shared.global [%0], [%1], 16, %2;"
                 :: "r"(dst), "l"(src), "r"(src_bytes) : "memory");
}
#define CP_COMMIT()  asm volatile("cp.async.commit_group;" ::: "memory")
#define CP_WAIT(n)   asm volatile("cp.async.wait_group %0;" :: "n"(n) : "memory")

__device__ __forceinline__ void split4(float4 v, uint2& hi, uint2& lo) {
    __nv_bfloat162 h0 = __floats2bfloat162_rn(v.x, v.y);
    __nv_bfloat162 h1 = __floats2bfloat162_rn(v.z, v.w);
    __nv_bfloat162 l0 = __floats2bfloat162_rn(v.x - __bfloat162float(h0.x),
                                              v.y - __bfloat162float(h0.y));
    __nv_bfloat162 l1 = __floats2bfloat162_rn(v.z - __bfloat162float(h1.x),
                                              v.w - __bfloat162float(h1.y));
    hi = make_uint2(*(uint32_t*)&h0, *(uint32_t*)&h1);
    lo = make_uint2(*(uint32_t*)&l0, *(uint32_t*)&l1);
}

// ---------------------------------------------------------------------------
// HMMA split-K GEMM, fp32 in / bf16 hi-lo split in place in smem.
// A [64][KA] fp32 row-major; W [KB][Nn] fp32 row-major.
// part[split][m][n] = sum_{k in split} A[m,k] * W[k,n].
// Tile M=64 x N=128 x Kchunk=64; 256 thr; warp = 32(M) x 32(N); 2 CTAs/SM.
// In-place layout after convert:
//   A row m: per 16-k segment s (64B): hi[16] @ m*272+s*64, lo[16] @ +32
//   B row k: per 32-n segment s (128B): hi[32] @ k*528+s*128, lo[32] @ +64
// ---------------------------------------------------------------------------
__global__ __launch_bounds__(256, 2) void gemm_hmma(
    const float* __restrict__ A, int KA,
    const float* __restrict__ W, int KB,
    float* __restrict__ part, int Nn, int span)
{
    extern __shared__ __align__(16) char sm[];
    const int tid = threadIdx.x, lane = tid & 31, w = tid >> 5;
    const int n0 = blockIdx.x * 128;
    const int k0 = blockIdx.y * span;
    const int kendA = min(k0 + span, KA);
    const int kendB = min(k0 + span, KB);
    const int nch = (kendA - k0 + 63) >> 6;
    const uint32_t sbase = smem_u32(sm);
    const int wm = (w & 1) * 32, wn = (w >> 1) * 32;

    float acc[2][4][4];
    #pragma unroll
    for (int i = 0; i < 2; i++)
        #pragma unroll
        for (int j = 0; j < 4; j++)
            #pragma unroll
            for (int e = 0; e < 4; e++) acc[i][j][e] = 0.f;

    const int aRow = lane & 15, aCol2 = (lane >> 4) * 16;   // aCol in bytes
    const int bRowT = lane & 15, bColT = (lane >> 4) * 8;
    const int bSeg = (w >> 1) * 128;                        // n-segment byte offset

    auto stage_cp = [&](int c) {
        const int kt = k0 + c * 64;
        const uint32_t sb = sbase + (uint32_t)(c & 1) * STG;
        #pragma unroll
        for (int u = 0; u < 4; u++) {          // A: 1024 granules of 4 floats
            int i = tid + u * 256;
            int m = i >> 4, g = i & 15;
            int gk = kt + g * 4;
            const float* src = A + (size_t)m * KA + gk;
            int ok = (gk + 4 <= kendA) ? 16 : 0;
            cp16(sb + (uint32_t)(m * 272 + g * 16), src, ok);
        }
        #pragma unroll
        for (int u = 0; u < 8; u++) {          // B: 2048 granules of 4 floats
            int j = tid + u * 256;
            int r = j >> 5, g = j & 31;
            int gk = kt + r, n = n0 + g * 4;
            const float* src = W + (size_t)gk * Nn + n;
            int ok = (gk < kendB && n + 4 <= Nn) ? 16 : 0;
            cp16(sb + OFF_B + (uint32_t)(r * 528 + g * 16), src, ok);
        }
        CP_COMMIT();
    };

    stage_cp(0);

    for (int c = 0; c < nch; c++) {
        if (c + 1 < nch) { stage_cp(c + 1); CP_WAIT(1); }
        else             { CP_WAIT(0); }
        __syncthreads();

        // ---- in-place convert fp32 -> bf16 hi/lo (each thread: own region)
        {
            char* sb = sm + (c & 1) * STG;
            // A: 16 floats (64 bytes) per thread
            char* pa = sb + (tid & 63) * 272 + (tid >> 6) * 64;
            float4 va[4];
            #pragma unroll
            for (int i = 0; i < 4; i++) va[i] = *(const float4*)(pa + i * 16);
            #pragma unroll
            for (int i = 0; i < 4; i++) {
                uint2 hi, lo;
                split4(va[i], hi, lo);
                *(uint2*)(pa + i * 8)      = hi;
                *(uint2*)(pa + 32 + i * 8) = lo;
            }
            // B: 32 floats (128 bytes) per thread
            char* pb = sb + OFF_B + (tid & 63) * 528 + (tid >> 6) * 128;
            float4 vb[8];
            #pragma unroll
            for (int i = 0; i < 8; i++) vb[i] = *(const float4*)(pb + i * 16);
            #pragma unroll
            for (int i = 0; i < 8; i++) {
                uint2 hi, lo;
                split4(vb[i], hi, lo);
                *(uint2*)(pb + i * 8)      = hi;
                *(uint2*)(pb + 64 + i * 8) = lo;
            }
        }
        __syncthreads();

        const uint32_t sb = sbase + (uint32_t)(c & 1) * STG;
        #pragma unroll
        for (int ks = 0; ks < 4; ks++) {
            uint32_t ah[2][4], al[2][4], bh[2][4], bl[2][4];
            #pragma unroll
            for (int mi = 0; mi < 2; mi++) {
                uint32_t ad = sb + (wm + mi * 16 + aRow) * 272 + ks * 64 + aCol2;
                LDX4(ah[mi], ad);
                LDX4(al[mi], ad + 32);
            }
            #pragma unroll
            for (int p = 0; p < 2; p++) {
                uint32_t bd = sb + OFF_B + (ks * 16 + bRowT) * 528 + bSeg
                            + (p * 16 + bColT) * 2;
                LDX4T(bh[p], bd);
                LDX4T(bl[p], bd + 64);
            }
            #pragma unroll
            for (int mi = 0; mi < 2; mi++)
                #pragma unroll
                for (int ni = 0; ni < 4; ni++) {
                    uint32_t* bhp = &bh[ni >> 1][(ni & 1) * 2];
                    uint32_t* blp = &bl[ni >> 1][(ni & 1) * 2];
                    MMA16816(acc[mi][ni], ah[mi], bhp);
                    MMA16816(acc[mi][ni], ah[mi], blp);
                    MMA16816(acc[mi][ni], al[mi], bhp);
                }
        }
        __syncthreads();
    }

    float* pb = part + (size_t)blockIdx.y * 64 * Nn;
    #pragma unroll
    for (int mi = 0; mi < 2; mi++)
        #pragma unroll
        for (int ni = 0; ni < 4; ni++) {
            int r0 = wm + mi * 16 + (lane >> 2);
            int cc = n0 + wn + ni * 8 + (lane & 3) * 2;
            if (cc < Nn) {
                pb[r0 * Nn + cc] = acc[mi][ni][0];
                pb[(r0 + 8) * Nn + cc] = acc[mi][ni][2];
            }
            if (cc + 1 < Nn) {
                pb[r0 * Nn + cc + 1] = acc[mi][ni][1];
                pb[(r0 + 8) * Nn + cc + 1] = acc[mi][ni][3];
            }
        }
}

// ---------------- prep: hpo column-max phase 1 (64-row strips) ----------------
__global__ void prep(const float* __restrict__ hpo)
{
    int cb = blockIdx.x;                       // 0..255
    int strip = cb >> 3;                       // 0..31
    int j = (cb & 7) * 256 + threadIdx.x;      // 0..2047
    const float* col = hpo + (size_t)(strip * 64) * NC + j;
    float m = col[0];
    #pragma unroll 8
    for (int i = 1; i < 64; i++)
        m = fmaxf(m, col[(size_t)i * NC]);
    g_cmax[strip][j] = m;
}

// ---------------- fuse1: reduce partials + bias + GELU + concat (fp32) ------
__global__ void fuse1(const float* __restrict__ b1, const float* __restrict__ expx)
{
    int idx = blockIdx.x * 256 + threadIdx.x;
    if (idx >= BB * KXP) return;
    int b = idx / KXP, n = idx - b * KXP;
    float v;
    if (n < HID) {
        float s = b1[n];
        #pragma unroll
        for (int p = 0; p < S1; p++) s += g_part1[p][b][n];
        v = 0.5f * s * (1.f + erff(s * 0.70710678118654752f));
    } else if (n < KX) {
        v = expx[b * EXPS + (n - HID)];
    } else {
        v = 0.f;
    }
    g_x[idx] = v;
}

// out[b,j] = sigmoid(sum + b2[j]) * max_i hpo[i,j]  (exact factorization)
__global__ void final_k(const float* __restrict__ b2, float* __restrict__ out)
{
    int j = blockIdx.x * 256 + threadIdx.x;
    int b = blockIdx.y;
    float m = g_cmax[0][j];
    #pragma unroll
    for (int p = 1; p < 32; p++) m = fmaxf(m, g_cmax[p][j]);
    float s = b2[j];
    #pragma unroll
    for (int p = 0; p < S2; p++) s += g_part2[p][b][j];
    out[b * NC + j] = m / (1.f + expf(-s));
}

// ---------------- launcher ----------------
extern "C" void kernel_launch(void* const* d_in, const int* in_sizes, int n_in,
                              void* d_out, int out_size)
{
    const float* gos  = (const float*)d_in[0];
    const float* expx = (const float*)d_in[1];
    const float* W1   = (const float*)d_in[2];
    const float* b1   = (const float*)d_in[3];
    const float* W2   = (const float*)d_in[4];
    const float* b2   = (const float*)d_in[5];
    const float* hpo  = (const float*)d_in[6];
    float* out = (float*)d_out;

    cudaFuncSetAttribute(gemm_hmma, cudaFuncAttributeMaxDynamicSharedMemorySize, SMEM_T);

    float *p1, *p2, *px;
    cudaGetSymbolAddress((void**)&p1, g_part1);
    cudaGetSymbolAddress((void**)&p2, g_part2);
    cudaGetSymbolAddress((void**)&px, g_x);

    prep<<<256, 256>>>(hpo);

    // GEMM1: (64 x 10000) @ W1(10000 x 1500), split-K 24 -> 288 blocks (2/SM)
    gemm_hmma<<<dim3(12, S1), 256, SMEM_T>>>(gos, INS, W1, INS, p1, HID, SPAN1);

    fuse1<<<(BB * KXP) / 256, 256>>>(b1, expx);

    // GEMM2: (64 x 1664pad) @ W2(1553 x 2048), split-K 18 -> 288 blocks
    gemm_hmma<<<dim3(16, S2), 256, SMEM_T>>>(px, KXP, W2, KX, p2, NC, SPAN2);

    final_k<<<dim3(NC / 256, BB), 256>>>(b2, out);
}

// round 8
// speedup vs baseline: 4.8339x; 1.3226x over previous
#include <cuda_runtime.h>
#include <cuda_fp16.h>
#include <math.h>
#include <stdint.h>

#define BB    64
#define INS   10000
#define EXPS  53
#define HID   1500
#define NC    2048
#define KX    1553
#define KXP   1664
#define S1    24
#define SPAN1 424           // 24*424 = 10176 >= 10000, mult of 8
#define S2    9
#define SPAN2 192           // 9*192 = 1728 >= 1664, mult of 8

// stage: A fp16 64 rows x 144B (9216) @0 ; B fp32 64 rows x 528B (33792) @9216
#define OFF_B  9216
#define STG    43008
#define SMEM_T 86016        // 2 stages -> 2 CTAs/SM

#define CONVA_BLKS 2500     // 2500*256 = BB*INS exactly

// ---------------- device scratch ----------------
__device__ __align__(16) __half g_Ah[BB * INS];
__device__ float g_part1[S1][BB][HID];
__device__ __align__(16) __half g_xh[BB * KXP];
__device__ float g_part2[S2][BB][NC];
__device__ float g_cmax[32][NC];

__device__ __forceinline__ uint32_t smem_u32(const void* p) {
    uint32_t a;
    asm("{ .reg .u64 t; cvta.to.shared.u64 t, %1; cvt.u32.u64 %0, t; }" : "=r"(a) : "l"(p));
    return a;
}
#define LDX4(r, addr)                                                        \
    asm volatile("ldmatrix.sync.aligned.m8n8.x4.shared.b16 {%0,%1,%2,%3}, [%4];" \
        : "=r"((r)[0]), "=r"((r)[1]), "=r"((r)[2]), "=r"((r)[3]) : "r"(addr))
#define LDX4T(r, addr)                                                       \
    asm volatile("ldmatrix.sync.aligned.m8n8.x4.trans.shared.b16 {%0,%1,%2,%3}, [%4];" \
        : "=r"((r)[0]), "=r"((r)[1]), "=r"((r)[2]), "=r"((r)[3]) : "r"(addr))
#define MMA16816(d, a, b)                                                    \
    asm volatile("mma.sync.aligned.m16n8k16.row.col.f32.f16.f16.f32 "       \
        "{%0,%1,%2,%3}, {%4,%5,%6,%7}, {%8,%9}, {%0,%1,%2,%3};"              \
        : "+f"((d)[0]), "+f"((d)[1]), "+f"((d)[2]), "+f"((d)[3])             \
        : "r"((a)[0]), "r"((a)[1]), "r"((a)[2]), "r"((a)[3]),                \
          "r"((b)[0]), "r"((b)[1]))
__device__ __forceinline__ void cp16(uint32_t dst, const void* src, int src_bytes) {
    asm volatile("cp.async.cg.shared.global [%0], [%1], 16, %2;"
                 :: "r"(dst), "l"(src), "r"(src_bytes) : "memory");
}
#define CP_COMMIT()  asm volatile("cp.async.commit_group;" ::: "memory")
#define CP_WAIT(n)   asm volatile("cp.async.wait_group %0;" :: "n"(n) : "memory")

// ---------------------------------------------------------------------------
// HMMA fp16 split-K GEMM. A: preconverted fp16 [64][KA], cp.async direct.
// B: fp32 W [KB][Nn] via cp.async, converted in place to fp16.
// part[split][m][n] = sum_{k in split} A[m,k] * W[k,n].
// Tile M=64 x N=128 x Kchunk=64; 256 thr; warp = 32(M) x 32(N); 2 CTAs/SM.
// B layout post-convert: row k, n-segment s(32 cols): fp16[32] @ k*528 + s*128.
// ---------------------------------------------------------------------------
__global__ __launch_bounds__(256, 2) void gemm_hmma(
    const __half* __restrict__ A, int KA,
    const float* __restrict__ W, int KB,
    float* __restrict__ part, int Nn, int span)
{
    extern __shared__ __align__(16) char sm[];
    const int tid = threadIdx.x, lane = tid & 31, w = tid >> 5;
    const int n0 = blockIdx.x * 128;
    const int k0 = blockIdx.y * span;
    const int kendA = min(k0 + span, KA);
    const int kendB = min(k0 + span, KB);
    const int nch = (kendA - k0 + 63) >> 6;
    const uint32_t sbase = smem_u32(sm);
    const int wm = (w & 1) * 32, wn = (w >> 1) * 32;

    float acc[2][4][4];
    #pragma unroll
    for (int i = 0; i < 2; i++)
        #pragma unroll
        for (int j = 0; j < 4; j++)
            #pragma unroll
            for (int e = 0; e < 4; e++) acc[i][j][e] = 0.f;

    const int aRow = lane & 15, aCol2 = (lane >> 4) * 16;   // bytes
    const int bRowT = lane & 15, bColT = (lane >> 4) * 8;
    const int bSeg = (w >> 1) * 128;

    auto stage_cp = [&](int c) {
        const int kt = k0 + c * 64;
        const uint32_t sb = sbase + (uint32_t)(c & 1) * STG;
        #pragma unroll
        for (int u = 0; u < 2; u++) {          // A fp16: 512 granules
            int i = tid + u * 256;
            int m = i >> 3, g = i & 7;
            int gk = kt + g * 8;
            const __half* src = A + (size_t)m * KA + gk;
            int ok = (gk + 8 <= kendA) ? 16 : 0;
            cp16(sb + (uint32_t)(m * 144 + g * 16), src, ok);
        }
        #pragma unroll
        for (int u = 0; u < 8; u++) {          // B fp32: 2048 granules
            int j = tid + u * 256;
            int r = j >> 5, g = j & 31;
            int gk = kt + r, n = n0 + g * 4;
            const float* src = W + (size_t)gk * Nn + n;
            int ok = (gk < kendB && n + 4 <= Nn) ? 16 : 0;
            cp16(sb + OFF_B + (uint32_t)(r * 528 + g * 16), src, ok);
        }
        CP_COMMIT();
    };

    stage_cp(0);

    for (int c = 0; c < nch; c++) {
        if (c + 1 < nch) { stage_cp(c + 1); CP_WAIT(1); }
        else             { CP_WAIT(0); }
        __syncthreads();

        // ---- in-place convert B fp32 -> fp16 (each thread owns 32 floats)
        {
            char* pb = sm + (c & 1) * STG + OFF_B + (tid & 63) * 528 + (tid >> 6) * 128;
            float4 v[8];
            #pragma unroll
            for (int i = 0; i < 8; i++) v[i] = *(const float4*)(pb + i * 16);
            #pragma unroll
            for (int i = 0; i < 4; i++) {
                __half2 h0 = __floats2half2_rn(v[2*i].x,   v[2*i].y);
                __half2 h1 = __floats2half2_rn(v[2*i].z,   v[2*i].w);
                __half2 h2 = __floats2half2_rn(v[2*i+1].x, v[2*i+1].y);
                __half2 h3 = __floats2half2_rn(v[2*i+1].z, v[2*i+1].w);
                uint4 o = make_uint4(*(uint32_t*)&h0, *(uint32_t*)&h1,
                                     *(uint32_t*)&h2, *(uint32_t*)&h3);
                *(uint4*)(pb + i * 16) = o;
            }
        }
        __syncthreads();

        const uint32_t sb = sbase + (uint32_t)(c & 1) * STG;
        #pragma unroll
        for (int ks = 0; ks < 4; ks++) {
            uint32_t af[2][4], bf[2][4];
            #pragma unroll
            for (int mi = 0; mi < 2; mi++)
                LDX4(af[mi], sb + (wm + mi * 16 + aRow) * 144 + ks * 32 + aCol2);
            #pragma unroll
            for (int p = 0; p < 2; p++)
                LDX4T(bf[p], sb + OFF_B + (ks * 16 + bRowT) * 528 + bSeg
                             + (p * 16 + bColT) * 2);
            #pragma unroll
            for (int mi = 0; mi < 2; mi++)
                #pragma unroll
                for (int ni = 0; ni < 4; ni++)
                    MMA16816(acc[mi][ni], af[mi], (&bf[ni >> 1][(ni & 1) * 2]));
        }
        __syncthreads();
    }

    float* pb = part + (size_t)blockIdx.y * 64 * Nn;
    #pragma unroll
    for (int mi = 0; mi < 2; mi++)
        #pragma unroll
        for (int ni = 0; ni < 4; ni++) {
            int r0 = wm + mi * 16 + (lane >> 2);
            int cc = n0 + wn + ni * 8 + (lane & 3) * 2;
            if (cc < Nn) {
                pb[r0 * Nn + cc] = acc[mi][ni][0];
                pb[(r0 + 8) * Nn + cc] = acc[mi][ni][2];
            }
            if (cc + 1 < Nn) {
                pb[r0 * Nn + cc + 1] = acc[mi][ni][1];
                pb[(r0 + 8) * Nn + cc + 1] = acc[mi][ni][3];
            }
        }
}

// ---------------- prep: convA(fp16) + hpo column-max strips ----------------
__global__ void prep(const float* __restrict__ A, const float* __restrict__ hpo)
{
    int bx = blockIdx.x;
    if (bx < CONVA_BLKS) {
        int idx = bx * 256 + threadIdx.x;
        g_Ah[idx] = __float2half(A[idx]);
    } else {
        int cb = bx - CONVA_BLKS;                  // 0..255
        int strip = cb >> 3;
        int j = (cb & 7) * 256 + threadIdx.x;
        const float* col = hpo + (size_t)(strip * 64) * NC + j;
        float m = col[0];
        #pragma unroll 8
        for (int i = 1; i < 64; i++)
            m = fmaxf(m, col[(size_t)i * NC]);
        g_cmax[strip][j] = m;
    }
}

// ---------------- fuse1: partials + bias + GELU + concat -> fp16 -----------
__global__ void fuse1(const float* __restrict__ b1, const float* __restrict__ expx)
{
    int idx = blockIdx.x * 256 + threadIdx.x;
    if (idx >= BB * KXP) return;
    int b = idx / KXP, n = idx - b * KXP;
    float v;
    if (n < HID) {
        float s = b1[n];
        #pragma unroll
        for (int p = 0; p < S1; p++) s += g_part1[p][b][n];
        v = 0.5f * s * (1.f + erff(s * 0.70710678118654752f));
    } else if (n < KX) {
        v = expx[b * EXPS + (n - HID)];
    } else {
        v = 0.f;
    }
    g_xh[idx] = __float2half(v);
}

// out[b,j] = sigmoid(sum + b2[j]) * max_i hpo[i,j]  (exact factorization)
__global__ void final_k(const float* __restrict__ b2, float* __restrict__ out)
{
    int j = blockIdx.x * 256 + threadIdx.x;
    int b = blockIdx.y;
    float m = g_cmax[0][j];
    #pragma unroll
    for (int p = 1; p < 32; p++) m = fmaxf(m, g_cmax[p][j]);
    float s = b2[j];
    #pragma unroll
    for (int p = 0; p < S2; p++) s += g_part2[p][b][j];
    out[b * NC + j] = m / (1.f + expf(-s));
}

// ---------------- launcher ----------------
extern "C" void kernel_launch(void* const* d_in, const int* in_sizes, int n_in,
                              void* d_out, int out_size)
{
    const float* gos  = (const float*)d_in[0];
    const float* expx = (const float*)d_in[1];
    const float* W1   = (const float*)d_in[2];
    const float* b1   = (const float*)d_in[3];
    const float* W2   = (const float*)d_in[4];
    const float* b2   = (const float*)d_in[5];
    const float* hpo  = (const float*)d_in[6];
    float* out = (float*)d_out;

    cudaFuncSetAttribute(gemm_hmma, cudaFuncAttributeMaxDynamicSharedMemorySize, SMEM_T);

    __half *ah, *xh;
    float *p1, *p2;
    cudaGetSymbolAddress((void**)&ah, g_Ah);
    cudaGetSymbolAddress((void**)&xh, g_xh);
    cudaGetSymbolAddress((void**)&p1, g_part1);
    cudaGetSymbolAddress((void**)&p2, g_part2);

    prep<<<CONVA_BLKS + 256, 256>>>(gos, hpo);

    // GEMM1: (64 x 10000) @ W1(10000 x 1500), split-K 24 -> 288 blocks
    gemm_hmma<<<dim3(12, S1), 256, SMEM_T>>>(ah, INS, W1, INS, p1, HID, SPAN1);

    fuse1<<<(BB * KXP) / 256, 256>>>(b1, expx);

    // GEMM2: (64 x 1664pad) @ W2(1553 x 2048), split-K 9 -> 144 blocks
    gemm_hmma<<<dim3(16, S2), 256, SMEM_T>>>(xh, KXP, W2, KX, p2, NC, SPAN2);

    final_k<<<dim3(NC / 256, BB), 256>>>(b2, out);
}